// round 2
// baseline (speedup 1.0000x reference)
#include <cuda_runtime.h>
#include <math.h>

// Problem constants (padded)
#define F1 128
#define MAXN 100096
#define MAXE 1700352

// ---------------- static device scratch (no allocations allowed) ----------------
__device__ float    g_h1[MAXN * F1];     // layer-1 projected features
__device__ float    g_out1[MAXN * F1];   // layer-1 aggregated output (pre-bias/relu)
__device__ float    g_s1s[MAXN];
__device__ float    g_s1d[MAXN];
__device__ unsigned g_m1[MAXN];          // encoded segment max
__device__ float    g_z1[MAXN];          // segment sum of exp
__device__ float    g_e1[MAXE];
__device__ float    g_ex1[MAXE];

__device__ float    g_h2[MAXN * 2];
__device__ float    g_s2s[MAXN];
__device__ float    g_s2d[MAXN];
__device__ unsigned g_m2[MAXN];
__device__ float    g_z2[MAXN];
__device__ float    g_e2[MAXE];
__device__ float    g_ex2[MAXE];

// ---------------- helpers ----------------
// Order-preserving encoding of float into unsigned (for atomicMax on floats incl. negatives)
__device__ __forceinline__ unsigned fenc(float f) {
    unsigned u = __float_as_uint(f);
    return (u & 0x80000000u) ? ~u : (u | 0x80000000u);
}
__device__ __forceinline__ float fdec(unsigned e) {
    return (e & 0x80000000u) ? __uint_as_float(e & 0x7fffffffu)
                             : __uint_as_float(~e);
}

// Edge i in [0, E) comes from edge_index (int32!); i in [E, E+N) is self-loop (i-E, i-E)
__device__ __forceinline__ void get_edge(const int* __restrict__ ei, int i, int E,
                                         int& s, int& d) {
    if (i < E) { s = ei[i]; d = ei[E + i]; }
    else       { s = d = i - E; }
}

// ---------------- kernels ----------------
__global__ void k_init(float* __restrict__ out, const float* __restrict__ b2, int N) {
    int i = blockIdx.x * blockDim.x + threadIdx.x;
    int stride = gridDim.x * blockDim.x;
    int nf = N * F1;
    for (int idx = i; idx < nf; idx += stride) g_out1[idx] = 0.f;
    for (int idx = i; idx < N; idx += stride) {
        g_m1[idx] = 0u; g_m2[idx] = 0u;
        g_z1[idx] = 0.f; g_z2[idx] = 0.f;
    }
    float b20 = b2[0], b21 = b2[1];
    for (int idx = i; idx < N; idx += stride) {
        out[idx * 2 + 0] = b20;
        out[idx * 2 + 1] = b21;
    }
}

// h1 = x @ W1 ; s1s = h1 . a_src1 ; s1d = h1 . a_dst1   (one block per node)
__global__ void k_gemm1(const float* __restrict__ x, const float* __restrict__ W1,
                        const float* __restrict__ a_src, const float* __restrict__ a_dst) {
    __shared__ float xs[F1];
    __shared__ float ps[4], qs[4];
    int n = blockIdx.x;
    int j = threadIdx.x;
    xs[j] = x[n * F1 + j];
    __syncthreads();
    float acc = 0.f;
#pragma unroll
    for (int k = 0; k < F1; k++) acc = fmaf(xs[k], W1[k * F1 + j], acc);
    g_h1[n * F1 + j] = acc;
    float p = acc * a_src[j];
    float q = acc * a_dst[j];
#pragma unroll
    for (int o = 16; o > 0; o >>= 1) {
        p += __shfl_down_sync(0xffffffffu, p, o);
        q += __shfl_down_sync(0xffffffffu, q, o);
    }
    if ((j & 31) == 0) { ps[j >> 5] = p; qs[j >> 5] = q; }
    __syncthreads();
    if (j == 0) g_s1s[n] = ps[0] + ps[1] + ps[2] + ps[3];
    if (j == 1) g_s1d[n] = qs[0] + qs[1] + qs[2] + qs[3];
}

// Per-edge raw score + leaky relu + segment max (encoded atomicMax)
template <int L>
__global__ void k_score(const int* __restrict__ ei, int E, int N) {
    int i = blockIdx.x * blockDim.x + threadIdx.x;
    int ET = E + N;
    if (i >= ET) return;
    int s, d;
    get_edge(ei, i, E, s, d);
    float e = (L == 1) ? (g_s1s[s] + g_s1d[d]) : (g_s2s[s] + g_s2d[d]);
    e = (e >= 0.f) ? e : 0.2f * e;
    if (L == 1) { g_e1[i] = e; atomicMax(&g_m1[d], fenc(e)); }
    else        { g_e2[i] = e; atomicMax(&g_m2[d], fenc(e)); }
}

// ex = exp(e - m[dst]); z[dst] += ex
template <int L>
__global__ void k_exp(const int* __restrict__ ei, int E, int N) {
    int i = blockIdx.x * blockDim.x + threadIdx.x;
    int ET = E + N;
    if (i >= ET) return;
    int s, d;
    get_edge(ei, i, E, s, d);
    (void)s;
    if (L == 1) {
        float ex = expf(g_e1[i] - fdec(g_m1[d]));
        g_ex1[i] = ex;
        atomicAdd(&g_z1[d], ex);
    } else {
        float ex = expf(g_e2[i] - fdec(g_m2[d]));
        g_ex2[i] = ex;
        atomicAdd(&g_z2[d], ex);
    }
}

// out1[dst] += alpha * h1[src]   (one block per edge, one thread per feature)
__global__ void k_scatter1(const int* __restrict__ ei, int E, int N) {
    int i = blockIdx.x;
    int f = threadIdx.x;
    int s, d;
    get_edge(ei, i, E, s, d);
    float alpha = g_ex1[i] / g_z1[d];
    atomicAdd(&g_out1[d * F1 + f], g_h1[s * F1 + f] * alpha);
}

// g = relu(out1 + b1); h2 = g @ W2; s2s/s2d  (one warp per node)
__global__ void k_node2(const float* __restrict__ b1, const float* __restrict__ W2,
                        const float* __restrict__ a_src2, const float* __restrict__ a_dst2,
                        int N) {
    int warp = (blockIdx.x * blockDim.x + threadIdx.x) >> 5;
    int lane = threadIdx.x & 31;
    if (warp >= N) return;
    float h0 = 0.f, h1v = 0.f;
#pragma unroll
    for (int t = 0; t < 4; t++) {
        int f = lane + t * 32;
        float g = g_out1[warp * F1 + f] + b1[f];
        g = (g > 0.f) ? g : 0.f;
        h0  = fmaf(g, W2[f * 2 + 0], h0);
        h1v = fmaf(g, W2[f * 2 + 1], h1v);
    }
#pragma unroll
    for (int o = 16; o > 0; o >>= 1) {
        h0  += __shfl_down_sync(0xffffffffu, h0, o);
        h1v += __shfl_down_sync(0xffffffffu, h1v, o);
    }
    if (lane == 0) {
        g_h2[warp * 2 + 0] = h0;
        g_h2[warp * 2 + 1] = h1v;
        g_s2s[warp] = h0 * a_src2[0] + h1v * a_src2[1];
        g_s2d[warp] = h0 * a_dst2[0] + h1v * a_dst2[1];
    }
}

// out[dst] += alpha2 * h2[src]
__global__ void k_scatter2(const int* __restrict__ ei, int E, int N,
                           float* __restrict__ out) {
    int i = blockIdx.x * blockDim.x + threadIdx.x;
    int ET = E + N;
    if (i >= ET) return;
    int s, d;
    get_edge(ei, i, E, s, d);
    float alpha = g_ex2[i] / g_z2[d];
    atomicAdd(&out[d * 2 + 0], g_h2[s * 2 + 0] * alpha);
    atomicAdd(&out[d * 2 + 1], g_h2[s * 2 + 1] * alpha);
}

// ---------------- launch ----------------
extern "C" void kernel_launch(void* const* d_in, const int* in_sizes, int n_in,
                              void* d_out, int out_size) {
    const float* x      = (const float*)d_in[0];
    const int*   ei     = (const int*)d_in[1];
    const float* W1     = (const float*)d_in[2];
    const float* a_src1 = (const float*)d_in[3];
    const float* a_dst1 = (const float*)d_in[4];
    const float* b1     = (const float*)d_in[5];
    const float* W2     = (const float*)d_in[6];
    const float* a_src2 = (const float*)d_in[7];
    const float* a_dst2 = (const float*)d_in[8];
    const float* b2     = (const float*)d_in[9];
    float*       out    = (float*)d_out;

    int N = in_sizes[0] / F1;
    int E = in_sizes[1] / 2;
    int ET = E + N;

    k_init<<<1024, 256>>>(out, b2, N);
    k_gemm1<<<N, F1>>>(x, W1, a_src1, a_dst1);

    int eb = (ET + 255) / 256;
    k_score<1><<<eb, 256>>>(ei, E, N);
    k_exp<1><<<eb, 256>>>(ei, E, N);
    k_scatter1<<<ET, F1>>>(ei, E, N);

    k_node2<<<(N * 32 + 127) / 128, 128>>>(b1, W2, a_src2, a_dst2, N);
    k_score<2><<<eb, 256>>>(ei, E, N);
    k_exp<2><<<eb, 256>>>(ei, E, N);
    k_scatter2<<<eb, 256>>>(ei, E, N, out);
}

// round 3
// speedup vs baseline: 3.5689x; 3.5689x over previous
#include <cuda_runtime.h>
#include <math.h>

#define F1 128
#define MAXN 100096
#define MAXE 1700352
#define NEG_INF (-__int_as_float(0x7f800000) * 1.0f)

// ---------------- static device scratch ----------------
__device__ float g_h1[MAXN * F1];
__device__ float g_s1s[MAXN];
__device__ float g_s1d[MAXN];
__device__ float g_h2[MAXN * 2];
__device__ float g_s2s[MAXN];
__device__ float g_s2d[MAXN];
__device__ int   g_deg[MAXN];
__device__ int   g_cnt[MAXN];
__device__ int   g_rowptr[MAXN + 1];
__device__ int   g_bsum[128];
__device__ int   g_bsumx[128];
__device__ int   g_csr_src[MAXE];

// ---------------- helpers ----------------
__device__ __forceinline__ void get_edge(const int* __restrict__ ei, int i, int E,
                                         int& s, int& d) {
    if (i < E) { s = ei[i]; d = ei[E + i]; }
    else       { s = d = i - E; }
}

// combine two online-softmax partials (m,z) <- (m,z) op (mo,zo)
__device__ __forceinline__ void sm_combine(float& m, float& z, float mo, float zo) {
    float M = fmaxf(m, mo);
    if (M > -INFINITY) {
        z = z * expf(m - M) + zo * expf(mo - M);
        m = M;
    } else {
        z = 0.f;
    }
}

// ---------------- kernels ----------------
__global__ void k_zero(int N) {
    int i = blockIdx.x * blockDim.x + threadIdx.x;
    int stride = gridDim.x * blockDim.x;
    for (int idx = i; idx < N; idx += stride) { g_deg[idx] = 0; g_cnt[idx] = 0; }
}

// h1 = x@W1, s1s = h1.a_src, s1d = h1.a_dst. Warp handles 4 nodes; lane t computes
// outputs [4t,4t+4) for each of those nodes with float4 W1 loads.
__global__ void k_gemm1(const float* __restrict__ x, const float* __restrict__ W1,
                        const float* __restrict__ a_src, const float* __restrict__ a_dst,
                        int N) {
    __shared__ float sh_x[32][F1];   // 32 nodes per block (8 warps x 4 nodes)
    int tid = threadIdx.x;
    int w = tid >> 5, t = tid & 31;
    int nodeBase = blockIdx.x * 32 + w * 4;

    const float4* x4 = (const float4*)x;
    const float4* W4 = (const float4*)W1;

    // stage x rows for this warp's 4 nodes
#pragma unroll
    for (int i = 0; i < 4; i++) {
        int n = nodeBase + i;
        if (n < N) {
            float4 v = x4[n * 32 + t];
            ((float4*)&sh_x[w * 4 + i][0])[t] = v;
        }
    }
    __syncwarp();

    float4 a0 = {0,0,0,0}, a1 = {0,0,0,0}, a2 = {0,0,0,0}, a3 = {0,0,0,0};
    const float4* sx0 = (const float4*)&sh_x[w * 4 + 0][0];
    const float4* sx1 = (const float4*)&sh_x[w * 4 + 1][0];
    const float4* sx2 = (const float4*)&sh_x[w * 4 + 2][0];
    const float4* sx3 = (const float4*)&sh_x[w * 4 + 3][0];

#pragma unroll 4
    for (int k4 = 0; k4 < 32; k4++) {
        float4 xv0 = sx0[k4], xv1 = sx1[k4], xv2 = sx2[k4], xv3 = sx3[k4];
#pragma unroll
        for (int kk = 0; kk < 4; kk++) {
            int k = k4 * 4 + kk;
            float4 wv = W4[k * 32 + t];
            float s0 = ((const float*)&xv0)[kk];
            float s1 = ((const float*)&xv1)[kk];
            float s2 = ((const float*)&xv2)[kk];
            float s3 = ((const float*)&xv3)[kk];
            a0.x = fmaf(s0, wv.x, a0.x); a0.y = fmaf(s0, wv.y, a0.y);
            a0.z = fmaf(s0, wv.z, a0.z); a0.w = fmaf(s0, wv.w, a0.w);
            a1.x = fmaf(s1, wv.x, a1.x); a1.y = fmaf(s1, wv.y, a1.y);
            a1.z = fmaf(s1, wv.z, a1.z); a1.w = fmaf(s1, wv.w, a1.w);
            a2.x = fmaf(s2, wv.x, a2.x); a2.y = fmaf(s2, wv.y, a2.y);
            a2.z = fmaf(s2, wv.z, a2.z); a2.w = fmaf(s2, wv.w, a2.w);
            a3.x = fmaf(s3, wv.x, a3.x); a3.y = fmaf(s3, wv.y, a3.y);
            a3.z = fmaf(s3, wv.z, a3.z); a3.w = fmaf(s3, wv.w, a3.w);
        }
    }

    float4 av = ((const float4*)a_src)[t];
    float4 dv = ((const float4*)a_dst)[t];
    float4* h1v = (float4*)g_h1;

#pragma unroll
    for (int i = 0; i < 4; i++) {
        int n = nodeBase + i;
        float4 acc = (i == 0) ? a0 : (i == 1) ? a1 : (i == 2) ? a2 : a3;
        if (n < N) h1v[n * 32 + t] = acc;
        float p = acc.x * av.x + acc.y * av.y + acc.z * av.z + acc.w * av.w;
        float q = acc.x * dv.x + acc.y * dv.y + acc.z * dv.z + acc.w * dv.w;
#pragma unroll
        for (int o = 16; o > 0; o >>= 1) {
            p += __shfl_down_sync(0xffffffffu, p, o);
            q += __shfl_down_sync(0xffffffffu, q, o);
        }
        if (t == 0 && n < N) { g_s1s[n] = p; g_s1d[n] = q; }
    }
}

__global__ void k_deg(const int* __restrict__ ei, int E, int N) {
    int i = blockIdx.x * blockDim.x + threadIdx.x;
    if (i >= E + N) return;
    int s, d; get_edge(ei, i, E, s, d); (void)s;
    atomicAdd(&g_deg[d], 1);
}

// two-level exclusive scan of g_deg -> g_rowptr
__global__ void k_scanA(int N) {
    __shared__ int sh[1024];
    int tid = threadIdx.x;
    int i = blockIdx.x * 1024 + tid;
    int v = (i < N) ? g_deg[i] : 0;
    sh[tid] = v;
    __syncthreads();
    for (int o = 1; o < 1024; o <<= 1) {
        int t = (tid >= o) ? sh[tid - o] : 0;
        __syncthreads();
        sh[tid] += t;
        __syncthreads();
    }
    if (i < N) g_rowptr[i] = sh[tid] - v;   // exclusive
    if (tid == 1023) g_bsum[blockIdx.x] = sh[1023];
}

__global__ void k_scanB(int NB) {
    __shared__ int sh[128];
    int tid = threadIdx.x;
    int v = (tid < NB) ? g_bsum[tid] : 0;
    sh[tid] = v;
    __syncthreads();
    for (int o = 1; o < 128; o <<= 1) {
        int t = (tid >= o) ? sh[tid - o] : 0;
        __syncthreads();
        sh[tid] += t;
        __syncthreads();
    }
    if (tid < NB) g_bsumx[tid] = sh[tid] - v;  // exclusive
}

__global__ void k_scanC(int N, int ET) {
    int i = blockIdx.x * blockDim.x + threadIdx.x;
    if (i < N) g_rowptr[i] += g_bsumx[i >> 10];
    if (i == 0) g_rowptr[N] = ET;
}

__global__ void k_fill(const int* __restrict__ ei, int E, int N) {
    int i = blockIdx.x * blockDim.x + threadIdx.x;
    if (i >= E + N) return;
    int s, d; get_edge(ei, i, E, s, d);
    int p = g_rowptr[d] + atomicAdd(&g_cnt[d], 1);
    g_csr_src[p] = s;
}

// Per-node: layer-1 softmax + weighted aggregation (atomic-free) + fused layer-2
// node transform: h2 = relu(agg + b1) @ W2, s2s/s2d.
__global__ void k_agg1(const float* __restrict__ b1, const float* __restrict__ W2,
                       const float* __restrict__ as2, const float* __restrict__ ad2) {
    __shared__ float sh_alpha[128];
    __shared__ int   sh_src[128];
    __shared__ float s_m[4], s_z[4];
    __shared__ float s_h[2][4];

    int n = blockIdx.x;
    int tid = threadIdx.x;
    int wid = tid >> 5, lane = tid & 31;
    int r0 = g_rowptr[n], r1 = g_rowptr[n + 1];
    float sd = g_s1d[n];

    // online (max, sumexp) over incoming edges
    float m = -INFINITY, z = 0.f;
    for (int p = r0 + tid; p < r1; p += 128) {
        float e = g_s1s[g_csr_src[p]] + sd;
        e = (e >= 0.f) ? e : 0.2f * e;
        if (e > m) { z = z * expf(m - e) + 1.f; m = e; }
        else        { z += expf(e - m); }
    }
#pragma unroll
    for (int o = 16; o > 0; o >>= 1) {
        float mo = __shfl_down_sync(0xffffffffu, m, o);
        float zo = __shfl_down_sync(0xffffffffu, z, o);
        sm_combine(m, z, mo, zo);
    }
    if (lane == 0) { s_m[wid] = m; s_z[wid] = z; }
    __syncthreads();
    if (tid < 32) {
        float m2 = (tid < 4) ? s_m[tid] : -INFINITY;
        float z2 = (tid < 4) ? s_z[tid] : 0.f;
#pragma unroll
        for (int o = 2; o > 0; o >>= 1) {
            float mo = __shfl_down_sync(0xffffffffu, m2, o);
            float zo = __shfl_down_sync(0xffffffffu, z2, o);
            sm_combine(m2, z2, mo, zo);
        }
        if (tid == 0) { s_m[0] = m2; s_z[0] = z2; }
    }
    __syncthreads();
    m = s_m[0]; z = s_z[0];

    // chunked: stage alpha + src in shared, then feature-parallel accumulate
    float acc = 0.f;   // feature tid
    for (int c0 = r0; c0 < r1; c0 += 128) {
        int p = c0 + tid;
        if (p < r1) {
            int s = g_csr_src[p];
            float e = g_s1s[s] + sd;
            e = (e >= 0.f) ? e : 0.2f * e;
            sh_alpha[tid] = expf(e - m) / z;
            sh_src[tid] = s;
        }
        __syncthreads();
        int cnt = min(128, r1 - c0);
#pragma unroll 4
        for (int j = 0; j < cnt; j++) {
            acc = fmaf(sh_alpha[j], g_h1[sh_src[j] * F1 + tid], acc);
        }
        __syncthreads();
    }

    // fused layer-2 node transform
    float g = acc + b1[tid];
    g = fmaxf(g, 0.f);
    float h0 = g * W2[tid * 2 + 0];
    float h1v = g * W2[tid * 2 + 1];
#pragma unroll
    for (int o = 16; o > 0; o >>= 1) {
        h0  += __shfl_down_sync(0xffffffffu, h0, o);
        h1v += __shfl_down_sync(0xffffffffu, h1v, o);
    }
    if (lane == 0) { s_h[0][wid] = h0; s_h[1][wid] = h1v; }
    __syncthreads();
    if (tid == 0) {
        float H0 = s_h[0][0] + s_h[0][1] + s_h[0][2] + s_h[0][3];
        float H1 = s_h[1][0] + s_h[1][1] + s_h[1][2] + s_h[1][3];
        g_h2[n * 2 + 0] = H0;
        g_h2[n * 2 + 1] = H1;
        g_s2s[n] = H0 * as2[0] + H1 * as2[1];
        g_s2d[n] = H0 * ad2[0] + H1 * ad2[1];
    }
}

// Layer-2 softmax + aggregation: one warp per node, atomic-free.
__global__ void k_agg2(const float* __restrict__ b2, float* __restrict__ out, int N) {
    int w = blockIdx.x * (blockDim.x >> 5) + (threadIdx.x >> 5);
    int lane = threadIdx.x & 31;
    if (w >= N) return;
    int r0 = g_rowptr[w], r1 = g_rowptr[w + 1];
    float sd = g_s2d[w];

    float m = -INFINITY, z = 0.f;
    for (int p = r0 + lane; p < r1; p += 32) {
        float e = g_s2s[g_csr_src[p]] + sd;
        e = (e >= 0.f) ? e : 0.2f * e;
        if (e > m) { z = z * expf(m - e) + 1.f; m = e; }
        else        { z += expf(e - m); }
    }
#pragma unroll
    for (int o = 16; o > 0; o >>= 1) {
        float mo = __shfl_down_sync(0xffffffffu, m, o);
        float zo = __shfl_down_sync(0xffffffffu, z, o);
        sm_combine(m, z, mo, zo);
    }
    m = __shfl_sync(0xffffffffu, m, 0);
    z = __shfl_sync(0xffffffffu, z, 0);

    float acc0 = 0.f, acc1 = 0.f;
    for (int p = r0 + lane; p < r1; p += 32) {
        int s = g_csr_src[p];
        float e = g_s2s[s] + sd;
        e = (e >= 0.f) ? e : 0.2f * e;
        float a = expf(e - m) / z;
        acc0 = fmaf(a, g_h2[s * 2 + 0], acc0);
        acc1 = fmaf(a, g_h2[s * 2 + 1], acc1);
    }
#pragma unroll
    for (int o = 16; o > 0; o >>= 1) {
        acc0 += __shfl_down_sync(0xffffffffu, acc0, o);
        acc1 += __shfl_down_sync(0xffffffffu, acc1, o);
    }
    if (lane == 0) {
        out[w * 2 + 0] = acc0 + b2[0];
        out[w * 2 + 1] = acc1 + b2[1];
    }
}

// ---------------- launch ----------------
extern "C" void kernel_launch(void* const* d_in, const int* in_sizes, int n_in,
                              void* d_out, int out_size) {
    const float* x      = (const float*)d_in[0];
    const int*   ei     = (const int*)d_in[1];
    const float* W1     = (const float*)d_in[2];
    const float* a_src1 = (const float*)d_in[3];
    const float* a_dst1 = (const float*)d_in[4];
    const float* b1     = (const float*)d_in[5];
    const float* W2     = (const float*)d_in[6];
    const float* a_src2 = (const float*)d_in[7];
    const float* a_dst2 = (const float*)d_in[8];
    const float* b2     = (const float*)d_in[9];
    float*       out    = (float*)d_out;

    int N = in_sizes[0] / F1;
    int E = in_sizes[1] / 2;
    int ET = E + N;
    int eb = (ET + 255) / 256;
    int NB = (N + 1023) / 1024;

    k_zero<<<256, 256>>>(N);
    k_gemm1<<<(N + 31) / 32, 256>>>(x, W1, a_src1, a_dst1, N);
    k_deg<<<eb, 256>>>(ei, E, N);
    k_scanA<<<NB, 1024>>>(N);
    k_scanB<<<1, 128>>>(NB);
    k_scanC<<<(N + 255) / 256, 256>>>(N, ET);
    k_fill<<<eb, 256>>>(ei, E, N);
    k_agg1<<<N, 128>>>(b1, W2, a_src2, a_dst2);
    k_agg2<<<(N + 7) / 8, 256>>>(b2, out, N);
}

// round 5
// speedup vs baseline: 4.2641x; 1.1948x over previous
#include <cuda_runtime.h>
#include <cuda_fp16.h>
#include <math.h>

#define F1 128
#define MAXN 100096
#define MAXE 1700352

// ---------------- static device scratch ----------------
__device__ __half g_h1h[MAXN * F1];      // fp16 projected features (gather table)
__device__ float  g_s1s[MAXN];
__device__ float  g_s1d[MAXN];
__device__ float  g_h2[MAXN * 2];
__device__ float  g_s2s[MAXN];
__device__ float  g_s2d[MAXN];
__device__ int    g_deg[MAXN];
__device__ int    g_cnt[MAXN];
__device__ int    g_rowptr[MAXN + 1];
__device__ int    g_bsum[128];
__device__ int    g_bsumx[128];
__device__ int    g_csr_src[MAXE];

// ---------------- helpers ----------------
__device__ __forceinline__ void get_edge(const int* __restrict__ ei, int i, int E,
                                         int& s, int& d) {
    if (i < E) { s = ei[i]; d = ei[E + i]; }
    else       { s = d = i - E; }
}
__device__ __forceinline__ float lrelu(float e) { return fmaxf(e, 0.2f * e); }

// ---------------- kernels ----------------
__global__ void k_zero(int N) {
    int i = blockIdx.x * blockDim.x + threadIdx.x;
    int stride = gridDim.x * blockDim.x;
    for (int idx = i; idx < N; idx += stride) { g_deg[idx] = 0; g_cnt[idx] = 0; }
}

// h1 = x@W1 (stored fp16), s1s/s1d in fp32. Warp handles 4 nodes; lane t computes
// outputs [4t,4t+4) with float4 W1 loads.
__global__ void k_gemm1(const float* __restrict__ x, const float* __restrict__ W1,
                        const float* __restrict__ a_src, const float* __restrict__ a_dst,
                        int N) {
    __shared__ float sh_x[32][F1];
    int tid = threadIdx.x;
    int w = tid >> 5, t = tid & 31;
    int nodeBase = blockIdx.x * 32 + w * 4;

    const float4* x4 = (const float4*)x;
    const float4* W4 = (const float4*)W1;

#pragma unroll
    for (int i = 0; i < 4; i++) {
        int n = nodeBase + i;
        if (n < N) ((float4*)&sh_x[w * 4 + i][0])[t] = x4[n * 32 + t];
    }
    __syncwarp();

    float4 a0 = {0,0,0,0}, a1 = {0,0,0,0}, a2 = {0,0,0,0}, a3 = {0,0,0,0};
    const float4* sx0 = (const float4*)&sh_x[w * 4 + 0][0];
    const float4* sx1 = (const float4*)&sh_x[w * 4 + 1][0];
    const float4* sx2 = (const float4*)&sh_x[w * 4 + 2][0];
    const float4* sx3 = (const float4*)&sh_x[w * 4 + 3][0];

#pragma unroll 4
    for (int k4 = 0; k4 < 32; k4++) {
        float4 xv0 = sx0[k4], xv1 = sx1[k4], xv2 = sx2[k4], xv3 = sx3[k4];
#pragma unroll
        for (int kk = 0; kk < 4; kk++) {
            int k = k4 * 4 + kk;
            float4 wv = W4[k * 32 + t];
            float s0 = ((const float*)&xv0)[kk];
            float s1 = ((const float*)&xv1)[kk];
            float s2 = ((const float*)&xv2)[kk];
            float s3 = ((const float*)&xv3)[kk];
            a0.x = fmaf(s0, wv.x, a0.x); a0.y = fmaf(s0, wv.y, a0.y);
            a0.z = fmaf(s0, wv.z, a0.z); a0.w = fmaf(s0, wv.w, a0.w);
            a1.x = fmaf(s1, wv.x, a1.x); a1.y = fmaf(s1, wv.y, a1.y);
            a1.z = fmaf(s1, wv.z, a1.z); a1.w = fmaf(s1, wv.w, a1.w);
            a2.x = fmaf(s2, wv.x, a2.x); a2.y = fmaf(s2, wv.y, a2.y);
            a2.z = fmaf(s2, wv.z, a2.z); a2.w = fmaf(s2, wv.w, a2.w);
            a3.x = fmaf(s3, wv.x, a3.x); a3.y = fmaf(s3, wv.y, a3.y);
            a3.z = fmaf(s3, wv.z, a3.z); a3.w = fmaf(s3, wv.w, a3.w);
        }
    }

    float4 av = ((const float4*)a_src)[t];
    float4 dv = ((const float4*)a_dst)[t];
    __half2* h1v = (__half2*)g_h1h;

#pragma unroll
    for (int i = 0; i < 4; i++) {
        int n = nodeBase + i;
        float4 acc = (i == 0) ? a0 : (i == 1) ? a1 : (i == 2) ? a2 : a3;
        if (n < N) {
            h1v[n * 64 + 2 * t + 0] = __floats2half2_rn(acc.x, acc.y);
            h1v[n * 64 + 2 * t + 1] = __floats2half2_rn(acc.z, acc.w);
        }
        float p = acc.x * av.x + acc.y * av.y + acc.z * av.z + acc.w * av.w;
        float q = acc.x * dv.x + acc.y * dv.y + acc.z * dv.z + acc.w * dv.w;
#pragma unroll
        for (int o = 16; o > 0; o >>= 1) {
            p += __shfl_down_sync(0xffffffffu, p, o);
            q += __shfl_down_sync(0xffffffffu, q, o);
        }
        if (t == 0 && n < N) { g_s1s[n] = p; g_s1d[n] = q; }
    }
}

__global__ void k_deg(const int* __restrict__ ei, int E, int N) {
    int i = blockIdx.x * blockDim.x + threadIdx.x;
    if (i >= E + N) return;
    int s, d; get_edge(ei, i, E, s, d); (void)s;
    atomicAdd(&g_deg[d], 1);
}

// exclusive scan of g_deg (shuffle-based), block partials to g_bsum
__global__ void k_scanA(int N) {
    __shared__ int wsum[32];
    int tid = threadIdx.x;
    int lane = tid & 31, wid = tid >> 5;
    int i = blockIdx.x * 1024 + tid;
    int v = (i < N) ? g_deg[i] : 0;
    int sc = v;
#pragma unroll
    for (int o = 1; o < 32; o <<= 1) {
        int t = __shfl_up_sync(0xffffffffu, sc, o);
        if (lane >= o) sc += t;
    }
    if (lane == 31) wsum[wid] = sc;
    __syncthreads();
    if (wid == 0) {
        int ws = wsum[lane];
#pragma unroll
        for (int o = 1; o < 32; o <<= 1) {
            int t = __shfl_up_sync(0xffffffffu, ws, o);
            if (lane >= o) ws += t;
        }
        wsum[lane] = ws;
    }
    __syncthreads();
    int off = (wid > 0) ? wsum[wid - 1] : 0;
    if (i < N) g_rowptr[i] = off + sc - v;   // exclusive
    if (tid == 1023) g_bsum[blockIdx.x] = off + sc;
}

__global__ void k_scanB(int NB) {
    __shared__ int sh[128];
    int tid = threadIdx.x;
    int v = (tid < NB) ? g_bsum[tid] : 0;
    sh[tid] = v;
    __syncthreads();
    for (int o = 1; o < 128; o <<= 1) {
        int t = (tid >= o) ? sh[tid - o] : 0;
        __syncthreads();
        sh[tid] += t;
        __syncthreads();
    }
    if (tid < NB) g_bsumx[tid] = sh[tid] - v;  // exclusive
}

__global__ void k_scanC(int N, int ET) {
    int i = blockIdx.x * blockDim.x + threadIdx.x;
    if (i < N) g_rowptr[i] += g_bsumx[i >> 10];
    if (i == 0) g_rowptr[N] = ET;
}

__global__ void k_fill(const int* __restrict__ ei, int E, int N) {
    int i = blockIdx.x * blockDim.x + threadIdx.x;
    if (i >= E + N) return;
    int s, d; get_edge(ei, i, E, s, d);
    int p = g_rowptr[d] + atomicAdd(&g_cnt[d], 1);
    g_csr_src[p] = s;
}

// Per-node layer-1: single-pass unnormalized softmax-weighted aggregation
// (no max shift, z accumulated alongside), then fused relu(+b1)@W2 epilogue.
__global__ void k_agg1(const float* __restrict__ b1, const float* __restrict__ W2,
                       const float* __restrict__ as2, const float* __restrict__ ad2) {
    __shared__ float sh_ex[128];
    __shared__ int   sh_src[128];
    __shared__ float s_red[4];
    __shared__ float s_h[2][4];

    int n = blockIdx.x;
    int tid = threadIdx.x;
    int wid = tid >> 5, lane = tid & 31;
    int r0 = g_rowptr[n], r1 = g_rowptr[n + 1];
    float sd = g_s1d[n];

    float zloc = 0.f;
    float acc = 0.f;     // feature tid accumulator (unnormalized)
    for (int c0 = r0; c0 < r1; c0 += 128) {
        int p = c0 + tid;
        if (p < r1) {
            int s = g_csr_src[p];
            float ex = __expf(lrelu(g_s1s[s] + sd));
            sh_ex[tid] = ex;
            sh_src[tid] = s;
            zloc += ex;
        }
        __syncthreads();
        int cnt = min(128, r1 - c0);
#pragma unroll 4
        for (int j = 0; j < cnt; j++) {
            acc = fmaf(sh_ex[j], __half2float(g_h1h[sh_src[j] * F1 + tid]), acc);
        }
        __syncthreads();
    }

    // block-reduce z
#pragma unroll
    for (int o = 16; o > 0; o >>= 1) zloc += __shfl_down_sync(0xffffffffu, zloc, o);
    if (lane == 0) s_red[wid] = zloc;
    __syncthreads();
    float z = s_red[0] + s_red[1] + s_red[2] + s_red[3];

    // fused layer-2 node transform
    float g = fmaxf(acc / z + b1[tid], 0.f);
    float h0 = g * W2[tid * 2 + 0];
    float h1v = g * W2[tid * 2 + 1];
#pragma unroll
    for (int o = 16; o > 0; o >>= 1) {
        h0  += __shfl_down_sync(0xffffffffu, h0, o);
        h1v += __shfl_down_sync(0xffffffffu, h1v, o);
    }
    if (lane == 0) { s_h[0][wid] = h0; s_h[1][wid] = h1v; }
    __syncthreads();
    if (tid == 0) {
        float H0 = s_h[0][0] + s_h[0][1] + s_h[0][2] + s_h[0][3];
        float H1 = s_h[1][0] + s_h[1][1] + s_h[1][2] + s_h[1][3];
        g_h2[n * 2 + 0] = H0;
        g_h2[n * 2 + 1] = H1;
        g_s2s[n] = H0 * as2[0] + H1 * as2[1];
        g_s2d[n] = H0 * ad2[0] + H1 * ad2[1];
    }
}

// Layer-2: one warp per node, single pass (acc and z together).
__global__ void k_agg2(const float* __restrict__ b2, float* __restrict__ out, int N) {
    int w = blockIdx.x * (blockDim.x >> 5) + (threadIdx.x >> 5);
    int lane = threadIdx.x & 31;
    if (w >= N) return;
    int r0 = g_rowptr[w], r1 = g_rowptr[w + 1];
    float sd = g_s2d[w];

    float z = 0.f, acc0 = 0.f, acc1 = 0.f;
    for (int p = r0 + lane; p < r1; p += 32) {
        int s = g_csr_src[p];
        float ex = __expf(lrelu(g_s2s[s] + sd));
        z += ex;
        acc0 = fmaf(ex, g_h2[s * 2 + 0], acc0);
        acc1 = fmaf(ex, g_h2[s * 2 + 1], acc1);
    }
#pragma unroll
    for (int o = 16; o > 0; o >>= 1) {
        z    += __shfl_down_sync(0xffffffffu, z, o);
        acc0 += __shfl_down_sync(0xffffffffu, acc0, o);
        acc1 += __shfl_down_sync(0xffffffffu, acc1, o);
    }
    if (lane == 0) {
        out[w * 2 + 0] = acc0 / z + b2[0];
        out[w * 2 + 1] = acc1 / z + b2[1];
    }
}

// ---------------- launch ----------------
extern "C" void kernel_launch(void* const* d_in, const int* in_sizes, int n_in,
                              void* d_out, int out_size) {
    const float* x      = (const float*)d_in[0];
    const int*   ei     = (const int*)d_in[1];
    const float* W1     = (const float*)d_in[2];
    const float* a_src1 = (const float*)d_in[3];
    const float* a_dst1 = (const float*)d_in[4];
    const float* b1     = (const float*)d_in[5];
    const float* W2     = (const float*)d_in[6];
    const float* a_src2 = (const float*)d_in[7];
    const float* a_dst2 = (const float*)d_in[8];
    const float* b2     = (const float*)d_in[9];
    float*       out    = (float*)d_out;

    int N = in_sizes[0] / F1;
    int E = in_sizes[1] / 2;
    int ET = E + N;
    int eb = (ET + 255) / 256;
    int NB = (N + 1023) / 1024;

    k_zero<<<256, 256>>>(N);
    k_gemm1<<<(N + 31) / 32, 256>>>(x, W1, a_src1, a_dst1, N);
    k_deg<<<eb, 256>>>(ei, E, N);
    k_scanA<<<NB, 1024>>>(N);
    k_scanB<<<1, 128>>>(NB);
    k_scanC<<<(N + 255) / 256, 256>>>(N, ET);
    k_fill<<<eb, 256>>>(ei, E, N);
    k_agg1<<<N, 128>>>(b1, W2, a_src2, a_dst2);
    k_agg2<<<(N + 7) / 8, 256>>>(b2, out, N);
}

// round 6
// speedup vs baseline: 5.6356x; 1.3217x over previous
#include <cuda_runtime.h>
#include <cuda_fp16.h>
#include <math.h>

#define F1 128
#define MAXN 100096
#define MAXE 1700352

// ---------------- static device scratch ----------------
__device__ __half g_h1h[MAXN * F1];      // fp16 projected features (gather table)
__device__ float  g_s1s[MAXN];
__device__ float  g_s1d[MAXN];
__device__ float  g_h2[MAXN * 2];
__device__ float  g_s2s[MAXN];
__device__ float  g_s2d[MAXN];
__device__ int    g_deg[MAXN];
__device__ int    g_cnt[MAXN];
__device__ int    g_rowptr[MAXN + 1];
__device__ int    g_bsum[128];
__device__ int    g_bsumx[128];
__device__ int    g_csr_src[MAXE];

__device__ __forceinline__ float lrelu(float e) { return fmaxf(e, 0.2f * e); }

// ---------------- kernels ----------------
// deg/cnt init to 1: slot 0 of every CSR row is reserved for the self-loop.
__global__ void k_zero(int N) {
    int i = blockIdx.x * blockDim.x + threadIdx.x;
    int stride = gridDim.x * blockDim.x;
    for (int idx = i; idx < N; idx += stride) { g_deg[idx] = 1; g_cnt[idx] = 1; }
}

// h1 = x@W1 (stored fp16), s1s/s1d in fp32. Warp handles 4 nodes; lane t computes
// outputs [4t,4t+4) with float4 W1 loads.
__global__ void k_gemm1(const float* __restrict__ x, const float* __restrict__ W1,
                        const float* __restrict__ a_src, const float* __restrict__ a_dst,
                        int N) {
    __shared__ float sh_x[32][F1];
    int tid = threadIdx.x;
    int w = tid >> 5, t = tid & 31;
    int nodeBase = blockIdx.x * 32 + w * 4;

    const float4* x4 = (const float4*)x;
    const float4* W4 = (const float4*)W1;

#pragma unroll
    for (int i = 0; i < 4; i++) {
        int n = nodeBase + i;
        if (n < N) ((float4*)&sh_x[w * 4 + i][0])[t] = x4[n * 32 + t];
    }
    __syncwarp();

    float4 a0 = {0,0,0,0}, a1 = {0,0,0,0}, a2 = {0,0,0,0}, a3 = {0,0,0,0};
    const float4* sx0 = (const float4*)&sh_x[w * 4 + 0][0];
    const float4* sx1 = (const float4*)&sh_x[w * 4 + 1][0];
    const float4* sx2 = (const float4*)&sh_x[w * 4 + 2][0];
    const float4* sx3 = (const float4*)&sh_x[w * 4 + 3][0];

#pragma unroll 4
    for (int k4 = 0; k4 < 32; k4++) {
        float4 xv0 = sx0[k4], xv1 = sx1[k4], xv2 = sx2[k4], xv3 = sx3[k4];
#pragma unroll
        for (int kk = 0; kk < 4; kk++) {
            int k = k4 * 4 + kk;
            float4 wv = W4[k * 32 + t];
            float s0 = ((const float*)&xv0)[kk];
            float s1 = ((const float*)&xv1)[kk];
            float s2 = ((const float*)&xv2)[kk];
            float s3 = ((const float*)&xv3)[kk];
            a0.x = fmaf(s0, wv.x, a0.x); a0.y = fmaf(s0, wv.y, a0.y);
            a0.z = fmaf(s0, wv.z, a0.z); a0.w = fmaf(s0, wv.w, a0.w);
            a1.x = fmaf(s1, wv.x, a1.x); a1.y = fmaf(s1, wv.y, a1.y);
            a1.z = fmaf(s1, wv.z, a1.z); a1.w = fmaf(s1, wv.w, a1.w);
            a2.x = fmaf(s2, wv.x, a2.x); a2.y = fmaf(s2, wv.y, a2.y);
            a2.z = fmaf(s2, wv.z, a2.z); a2.w = fmaf(s2, wv.w, a2.w);
            a3.x = fmaf(s3, wv.x, a3.x); a3.y = fmaf(s3, wv.y, a3.y);
            a3.z = fmaf(s3, wv.z, a3.z); a3.w = fmaf(s3, wv.w, a3.w);
        }
    }

    float4 av = ((const float4*)a_src)[t];
    float4 dv = ((const float4*)a_dst)[t];
    __half2* h1v = (__half2*)g_h1h;

#pragma unroll
    for (int i = 0; i < 4; i++) {
        int n = nodeBase + i;
        float4 acc = (i == 0) ? a0 : (i == 1) ? a1 : (i == 2) ? a2 : a3;
        if (n < N) {
            h1v[n * 64 + 2 * t + 0] = __floats2half2_rn(acc.x, acc.y);
            h1v[n * 64 + 2 * t + 1] = __floats2half2_rn(acc.z, acc.w);
        }
        float p = acc.x * av.x + acc.y * av.y + acc.z * av.z + acc.w * av.w;
        float q = acc.x * dv.x + acc.y * dv.y + acc.z * dv.z + acc.w * dv.w;
#pragma unroll
        for (int o = 16; o > 0; o >>= 1) {
            p += __shfl_down_sync(0xffffffffu, p, o);
            q += __shfl_down_sync(0xffffffffu, q, o);
        }
        if (t == 0 && n < N) { g_s1s[n] = p; g_s1d[n] = q; }
    }
}

// degree histogram over real edges only (dst half of edge_index)
__global__ void k_deg(const int* __restrict__ ei, int E) {
    int i = blockIdx.x * blockDim.x + threadIdx.x;
    if (i >= E) return;
    atomicAdd(&g_deg[ei[E + i]], 1);
}

// exclusive scan of g_deg (shuffle-based), block partials to g_bsum
__global__ void k_scanA(int N) {
    __shared__ int wsum[32];
    int tid = threadIdx.x;
    int lane = tid & 31, wid = tid >> 5;
    int i = blockIdx.x * 1024 + tid;
    int v = (i < N) ? g_deg[i] : 0;
    int sc = v;
#pragma unroll
    for (int o = 1; o < 32; o <<= 1) {
        int t = __shfl_up_sync(0xffffffffu, sc, o);
        if (lane >= o) sc += t;
    }
    if (lane == 31) wsum[wid] = sc;
    __syncthreads();
    if (wid == 0) {
        int ws = wsum[lane];
#pragma unroll
        for (int o = 1; o < 32; o <<= 1) {
            int t = __shfl_up_sync(0xffffffffu, ws, o);
            if (lane >= o) ws += t;
        }
        wsum[lane] = ws;
    }
    __syncthreads();
    int off = (wid > 0) ? wsum[wid - 1] : 0;
    if (i < N) g_rowptr[i] = off + sc - v;   // exclusive (block-local)
    if (tid == 1023) g_bsum[blockIdx.x] = off + sc;
}

__global__ void k_scanB(int NB) {
    __shared__ int sh[128];
    int tid = threadIdx.x;
    int v = (tid < NB) ? g_bsum[tid] : 0;
    sh[tid] = v;
    __syncthreads();
    for (int o = 1; o < 128; o <<= 1) {
        int t = (tid >= o) ? sh[tid - o] : 0;
        __syncthreads();
        sh[tid] += t;
        __syncthreads();
    }
    if (tid < NB) g_bsumx[tid] = sh[tid] - v;  // exclusive
}

// finalize rowptr AND plant self-loop in reserved slot 0 of each row
__global__ void k_scanC(int N, int ET) {
    int i = blockIdx.x * blockDim.x + threadIdx.x;
    if (i < N) {
        int rp = g_rowptr[i] + g_bsumx[i >> 10];
        g_rowptr[i] = rp;
        g_csr_src[rp] = i;        // self-loop
    }
    if (i == 0) g_rowptr[N] = ET;
}

// scatter real edges into CSR (slots 1..deg)
__global__ void k_fill(const int* __restrict__ ei, int E) {
    int i = blockIdx.x * blockDim.x + threadIdx.x;
    if (i >= E) return;
    int s = ei[i], d = ei[E + i];
    int p = g_rowptr[d] + atomicAdd(&g_cnt[d], 1);
    g_csr_src[p] = s;
}

// Layer-1 aggregation: ONE WARP per node. Chunk of 32 edges: lane computes its
// edge's exp weight; then 32 broadcast steps where the full warp loads the
// 256-byte h1 row (8 B/lane) and FMAs. Fused relu(+b1)@W2 epilogue.
__global__ void k_agg1(const float* __restrict__ b1, const float* __restrict__ W2,
                       const float* __restrict__ as2, const float* __restrict__ ad2,
                       int N) {
    int w = blockIdx.x * (blockDim.x >> 5) + (threadIdx.x >> 5);
    int lane = threadIdx.x & 31;
    if (w >= N) return;
    int r0 = g_rowptr[w], r1 = g_rowptr[w + 1];
    float sd = g_s1d[w];

    float z = 0.f;
    float acc0 = 0.f, acc1 = 0.f, acc2 = 0.f, acc3 = 0.f;
    const uint2* h1v = (const uint2*)g_h1h;   // 32 x uint2 per row

    for (int c0 = r0; c0 < r1; c0 += 32) {
        int p = c0 + lane;
        int s = 0;
        float ex = 0.f;
        if (p < r1) {
            s = g_csr_src[p];
            ex = __expf(lrelu(g_s1s[s] + sd));
            z += ex;
        }
        int cnt = min(32, r1 - c0);
#pragma unroll 4
        for (int j = 0; j < cnt; j++) {
            float a  = __shfl_sync(0xffffffffu, ex, j);
            int   sj = __shfl_sync(0xffffffffu, s, j);
            uint2 hv = h1v[sj * 32 + lane];
            float2 f01 = __half22float2(*(__half2*)&hv.x);
            float2 f23 = __half22float2(*(__half2*)&hv.y);
            acc0 = fmaf(a, f01.x, acc0);
            acc1 = fmaf(a, f01.y, acc1);
            acc2 = fmaf(a, f23.x, acc2);
            acc3 = fmaf(a, f23.y, acc3);
        }
    }
#pragma unroll
    for (int o = 16; o > 0; o >>= 1) z += __shfl_xor_sync(0xffffffffu, z, o);

    // epilogue: features f = lane*4 + {0..3}
    float4 bv = ((const float4*)b1)[lane];
    float g0 = fmaxf(acc0 / z + bv.x, 0.f);
    float g1 = fmaxf(acc1 / z + bv.y, 0.f);
    float g2 = fmaxf(acc2 / z + bv.z, 0.f);
    float g3 = fmaxf(acc3 / z + bv.w, 0.f);
    const float4* W24 = (const float4*)W2;    // [f][2] layout
    float4 wA = W24[lane * 2 + 0];            // f, f+1
    float4 wB = W24[lane * 2 + 1];            // f+2, f+3
    float h0 = g0 * wA.x + g1 * wA.z + g2 * wB.x + g3 * wB.z;
    float h1 = g0 * wA.y + g1 * wA.w + g2 * wB.y + g3 * wB.w;
#pragma unroll
    for (int o = 16; o > 0; o >>= 1) {
        h0 += __shfl_down_sync(0xffffffffu, h0, o);
        h1 += __shfl_down_sync(0xffffffffu, h1, o);
    }
    if (lane == 0) {
        g_h2[w * 2 + 0] = h0;
        g_h2[w * 2 + 1] = h1;
        g_s2s[w] = h0 * as2[0] + h1 * as2[1];
        g_s2d[w] = h0 * ad2[0] + h1 * ad2[1];
    }
}

// Layer-2: one warp per node, single pass (acc and z together).
__global__ void k_agg2(const float* __restrict__ b2, float* __restrict__ out, int N) {
    int w = blockIdx.x * (blockDim.x >> 5) + (threadIdx.x >> 5);
    int lane = threadIdx.x & 31;
    if (w >= N) return;
    int r0 = g_rowptr[w], r1 = g_rowptr[w + 1];
    float sd = g_s2d[w];

    float z = 0.f, acc0 = 0.f, acc1 = 0.f;
    for (int p = r0 + lane; p < r1; p += 32) {
        int s = g_csr_src[p];
        float ex = __expf(lrelu(g_s2s[s] + sd));
        z += ex;
        acc0 = fmaf(ex, g_h2[s * 2 + 0], acc0);
        acc1 = fmaf(ex, g_h2[s * 2 + 1], acc1);
    }
#pragma unroll
    for (int o = 16; o > 0; o >>= 1) {
        z    += __shfl_down_sync(0xffffffffu, z, o);
        acc0 += __shfl_down_sync(0xffffffffu, acc0, o);
        acc1 += __shfl_down_sync(0xffffffffu, acc1, o);
    }
    if (lane == 0) {
        out[w * 2 + 0] = acc0 / z + b2[0];
        out[w * 2 + 1] = acc1 / z + b2[1];
    }
}

// ---------------- launch ----------------
extern "C" void kernel_launch(void* const* d_in, const int* in_sizes, int n_in,
                              void* d_out, int out_size) {
    const float* x      = (const float*)d_in[0];
    const int*   ei     = (const int*)d_in[1];
    const float* W1     = (const float*)d_in[2];
    const float* a_src1 = (const float*)d_in[3];
    const float* a_dst1 = (const float*)d_in[4];
    const float* b1     = (const float*)d_in[5];
    const float* W2     = (const float*)d_in[6];
    const float* a_src2 = (const float*)d_in[7];
    const float* a_dst2 = (const float*)d_in[8];
    const float* b2     = (const float*)d_in[9];
    float*       out    = (float*)d_out;

    int N = in_sizes[0] / F1;
    int E = in_sizes[1] / 2;
    int ET = E + N;
    int NB = (N + 1023) / 1024;

    k_zero<<<256, 256>>>(N);
    k_gemm1<<<(N + 31) / 32, 256>>>(x, W1, a_src1, a_dst1, N);
    k_deg<<<(E + 255) / 256, 256>>>(ei, E);
    k_scanA<<<NB, 1024>>>(N);
    k_scanB<<<1, 128>>>(NB);
    k_scanC<<<(N + 255) / 256, 256>>>(N, ET);
    k_fill<<<(E + 255) / 256, 256>>>(ei, E);
    k_agg1<<<(N + 7) / 8, 256>>>(b1, W2, a_src2, a_dst2, N);
    k_agg2<<<(N + 7) / 8, 256>>>(b2, out, N);
}

// round 8
// speedup vs baseline: 8.0418x; 1.4270x over previous
#include <cuda_runtime.h>
#include <cuda_fp16.h>
#include <math.h>

#define F1 128
#define MAXN 100096
#define MAXE 1700352

// ---------------- static device scratch ----------------
__device__ __half g_h1h[MAXN * F1];      // fp16 projected features (gather table)
__device__ __half g_W1f[128 * 128];      // W1 fp16, pre-swizzled into mma B-fragment order
__device__ float  g_s1s[MAXN];
__device__ float  g_s1d[MAXN];
__device__ float4 g_n2[MAXN];            // packed layer-2 node data {h0, h1, s2s, s2d}
__device__ int    g_deg[MAXN];
__device__ int    g_cnt[MAXN];
__device__ int    g_rowptr[MAXN + 1];
__device__ int    g_bsum[128];
__device__ int    g_bsumx[128];
__device__ int    g_csr_src[MAXE];

__device__ __forceinline__ float lrelu(float e) { return fmaxf(e, 0.2f * e); }

// ---------------- kernels ----------------
// deg/cnt init to 1: slot 0 of every CSR row is reserved for the self-loop.
__global__ void k_zero(int N) {
    int i = blockIdx.x * blockDim.x + threadIdx.x;
    int stride = gridDim.x * blockDim.x;
    for (int idx = i; idx < N; idx += stride) { g_deg[idx] = 1; g_cnt[idx] = 1; }
}

// Pre-swizzle W1 into B-fragment order for mma.m16n8k16:
// unit u = (ks, nt, lane); 4 halves: rows k0+(l%4)*2+{0,1} and +8, col nt*8+l/4.
__global__ void k_prepW(const float* __restrict__ W1) {
    int u = blockIdx.x * blockDim.x + threadIdx.x;   // 4096 units
    if (u >= 4096) return;
    int lane = u & 31, nt = (u >> 5) & 15, ks = u >> 9;
    int kb = ks * 16 + (lane & 3) * 2;
    int n  = nt * 8 + (lane >> 2);
    __half h0 = __float2half_rn(W1[(kb + 0) * 128 + n]);
    __half h1 = __float2half_rn(W1[(kb + 1) * 128 + n]);
    __half h2 = __float2half_rn(W1[(kb + 8) * 128 + n]);
    __half h3 = __float2half_rn(W1[(kb + 9) * 128 + n]);
    __half2* out = (__half2*)g_W1f;
    out[u * 2 + 0] = __halves2half2(h0, h1);
    out[u * 2 + 1] = __halves2half2(h2, h3);
}

// Tensor-core GEMM: 64 nodes x 128 out per block (256 thr, 8 warps).
// Warp w: m-tile = w&3 (16 nodes), n-half = w>>2 (64 cols = 8 n-tiles).
// Dynamic shared: x tile (17408 B) + W1 fragments (32768 B) + score partials (1024 B).
#define XROW 136   // padded smem row stride in halves (conflict-free frag loads)
#define GEMM1_SMEM (64 * XROW * 2 + 128 * 128 * 2 + 2 * 64 * 2 * 4)
__global__ void k_gemm1(const float* __restrict__ x,
                        const float* __restrict__ a_src, const float* __restrict__ a_dst,
                        int N) {
    extern __shared__ __align__(16) char dynsmem[];
    __half* sxh = (__half*)dynsmem;                              // 64*XROW halves
    __half* sW1 = (__half*)(dynsmem + 64 * XROW * 2);            // 128*128 halves
    float*  sps = (float*)(dynsmem + 64 * XROW * 2 + 128 * 128 * 2); // [64][2]
    float*  spd = sps + 128;                                     // [64][2]

    int tid = threadIdx.x;
    int nbase = blockIdx.x * 64;

    // stage x tile as fp16 (zero-padded past N)
    const float4* x4 = (const float4*)x;
#pragma unroll
    for (int i = 0; i < 8; i++) {
        int f = tid + 256 * i;           // 2048 float4 per tile
        int row = f >> 5, kc = (f & 31) * 4;
        int n = nbase + row;
        float4 v = (n < N) ? x4[n * 32 + (f & 31)] : make_float4(0.f, 0.f, 0.f, 0.f);
        __half2 lo = __floats2half2_rn(v.x, v.y);
        __half2 hi = __floats2half2_rn(v.z, v.w);
        *(__half2*)&sxh[row * XROW + kc]     = lo;
        *(__half2*)&sxh[row * XROW + kc + 2] = hi;
    }
    // stage pre-swizzled W1 fragments (linear copy, L2-resident)
    {
        const uint2* src = (const uint2*)g_W1f;
        uint2* dst = (uint2*)sW1;
#pragma unroll
        for (int i = 0; i < 16; i++) dst[tid + 256 * i] = src[tid + 256 * i];
    }
    __syncthreads();

    int w = tid >> 5, lane = tid & 31;
    int mt16 = (w & 3) * 16;
    int nhalf = w >> 2;
    int r = lane >> 2, cq = (lane & 3) * 2;

    float c[8][4];
#pragma unroll
    for (int nt = 0; nt < 8; nt++)
#pragma unroll
        for (int j = 0; j < 4; j++) c[nt][j] = 0.f;

    const uint2* W1f2 = (const uint2*)sW1;
#pragma unroll
    for (int ks = 0; ks < 8; ks++) {
        int k0 = ks * 16;
        unsigned a0 = *(const unsigned*)&sxh[(mt16 + r) * XROW + k0 + cq];
        unsigned a1 = *(const unsigned*)&sxh[(mt16 + r + 8) * XROW + k0 + cq];
        unsigned a2 = *(const unsigned*)&sxh[(mt16 + r) * XROW + k0 + cq + 8];
        unsigned a3 = *(const unsigned*)&sxh[(mt16 + r + 8) * XROW + k0 + cq + 8];
#pragma unroll
        for (int nt = 0; nt < 8; nt++) {
            uint2 b = W1f2[(ks * 16 + nhalf * 8 + nt) * 32 + lane];
            asm volatile(
                "mma.sync.aligned.m16n8k16.row.col.f32.f16.f16.f32 "
                "{%0,%1,%2,%3}, {%4,%5,%6,%7}, {%8,%9}, {%0,%1,%2,%3};"
                : "+f"(c[nt][0]), "+f"(c[nt][1]), "+f"(c[nt][2]), "+f"(c[nt][3])
                : "r"(a0), "r"(a1), "r"(a2), "r"(a3), "r"(b.x), "r"(b.y));
        }
    }

    // epilogue: store h1 (fp16) + per-row score partials
    int node0 = nbase + mt16 + r;
    int node1 = node0 + 8;
    float p0 = 0.f, q0 = 0.f, p1 = 0.f, q1 = 0.f;
    __half2* h1v = (__half2*)g_h1h;
#pragma unroll
    for (int nt = 0; nt < 8; nt++) {
        int col = nhalf * 64 + nt * 8 + cq;
        float as0 = a_src[col], as1 = a_src[col + 1];
        float ad0 = a_dst[col], ad1 = a_dst[col + 1];
        p0 += c[nt][0] * as0 + c[nt][1] * as1;
        q0 += c[nt][0] * ad0 + c[nt][1] * ad1;
        p1 += c[nt][2] * as0 + c[nt][3] * as1;
        q1 += c[nt][2] * ad0 + c[nt][3] * ad1;
        if (node0 < N) h1v[node0 * 64 + (col >> 1)] = __floats2half2_rn(c[nt][0], c[nt][1]);
        if (node1 < N) h1v[node1 * 64 + (col >> 1)] = __floats2half2_rn(c[nt][2], c[nt][3]);
    }
#pragma unroll
    for (int o = 1; o <= 2; o <<= 1) {
        p0 += __shfl_xor_sync(0xffffffffu, p0, o);
        q0 += __shfl_xor_sync(0xffffffffu, q0, o);
        p1 += __shfl_xor_sync(0xffffffffu, p1, o);
        q1 += __shfl_xor_sync(0xffffffffu, q1, o);
    }
    if ((lane & 3) == 0) {
        sps[(mt16 + r) * 2 + nhalf] = p0;     spd[(mt16 + r) * 2 + nhalf] = q0;
        sps[(mt16 + r + 8) * 2 + nhalf] = p1; spd[(mt16 + r + 8) * 2 + nhalf] = q1;
    }
    __syncthreads();
    if (tid < 64) {
        int n = nbase + tid;
        if (n < N) {
            g_s1s[n] = sps[tid * 2 + 0] + sps[tid * 2 + 1];
            g_s1d[n] = spd[tid * 2 + 0] + spd[tid * 2 + 1];
        }
    }
}

// degree histogram over real edges only (dst half of edge_index)
__global__ void k_deg(const int* __restrict__ ei, int E) {
    int i = blockIdx.x * blockDim.x + threadIdx.x;
    if (i >= E) return;
    atomicAdd(&g_deg[ei[E + i]], 1);
}

// exclusive scan of g_deg (shuffle-based), block partials to g_bsum
__global__ void k_scanA(int N) {
    __shared__ int wsum[32];
    int tid = threadIdx.x;
    int lane = tid & 31, wid = tid >> 5;
    int i = blockIdx.x * 1024 + tid;
    int v = (i < N) ? g_deg[i] : 0;
    int sc = v;
#pragma unroll
    for (int o = 1; o < 32; o <<= 1) {
        int t = __shfl_up_sync(0xffffffffu, sc, o);
        if (lane >= o) sc += t;
    }
    if (lane == 31) wsum[wid] = sc;
    __syncthreads();
    if (wid == 0) {
        int ws = wsum[lane];
#pragma unroll
        for (int o = 1; o < 32; o <<= 1) {
            int t = __shfl_up_sync(0xffffffffu, ws, o);
            if (lane >= o) ws += t;
        }
        wsum[lane] = ws;
    }
    __syncthreads();
    int off = (wid > 0) ? wsum[wid - 1] : 0;
    if (i < N) g_rowptr[i] = off + sc - v;   // exclusive (block-local)
    if (tid == 1023) g_bsum[blockIdx.x] = off + sc;
}

__global__ void k_scanB(int NB) {
    __shared__ int sh[128];
    int tid = threadIdx.x;
    int v = (tid < NB) ? g_bsum[tid] : 0;
    sh[tid] = v;
    __syncthreads();
    for (int o = 1; o < 128; o <<= 1) {
        int t = (tid >= o) ? sh[tid - o] : 0;
        __syncthreads();
        sh[tid] += t;
        __syncthreads();
    }
    if (tid < NB) g_bsumx[tid] = sh[tid] - v;  // exclusive
}

// finalize rowptr AND plant self-loop in reserved slot 0 of each row
__global__ void k_scanC(int N, int ET) {
    int i = blockIdx.x * blockDim.x + threadIdx.x;
    if (i < N) {
        int rp = g_rowptr[i] + g_bsumx[i >> 10];
        g_rowptr[i] = rp;
        g_csr_src[rp] = i;        // self-loop
    }
    if (i == 0) g_rowptr[N] = ET;
}

// scatter real edges into CSR (slots 1..deg)
__global__ void k_fill(const int* __restrict__ ei, int E) {
    int i = blockIdx.x * blockDim.x + threadIdx.x;
    if (i >= E) return;
    int s = ei[i], d = ei[E + i];
    int p = g_rowptr[d] + atomicAdd(&g_cnt[d], 1);
    g_csr_src[p] = s;
}

// Layer-1 aggregation: ONE WARP per node, shuffle-broadcast alphas, 8 B/lane
// row loads. Fused relu(+b1)@W2 epilogue writes packed g_n2.
__global__ void k_agg1(const float* __restrict__ b1, const float* __restrict__ W2,
                       const float* __restrict__ as2, const float* __restrict__ ad2,
                       int N) {
    int w = blockIdx.x * (blockDim.x >> 5) + (threadIdx.x >> 5);
    int lane = threadIdx.x & 31;
    if (w >= N) return;
    int r0 = g_rowptr[w], r1 = g_rowptr[w + 1];
    float sd = g_s1d[w];

    float z = 0.f;
    float acc0 = 0.f, acc1 = 0.f, acc2 = 0.f, acc3 = 0.f;
    const uint2* h1v = (const uint2*)g_h1h;   // 32 x uint2 per row

    for (int c0 = r0; c0 < r1; c0 += 32) {
        int p = c0 + lane;
        int s = 0;
        float ex = 0.f;
        if (p < r1) {
            s = g_csr_src[p];
            ex = __expf(lrelu(g_s1s[s] + sd));
            z += ex;
        }
        int cnt = min(32, r1 - c0);
#pragma unroll 4
        for (int j = 0; j < cnt; j++) {
            float a  = __shfl_sync(0xffffffffu, ex, j);
            int   sj = __shfl_sync(0xffffffffu, s, j);
            uint2 hv = h1v[sj * 32 + lane];
            float2 f01 = __half22float2(*(__half2*)&hv.x);
            float2 f23 = __half22float2(*(__half2*)&hv.y);
            acc0 = fmaf(a, f01.x, acc0);
            acc1 = fmaf(a, f01.y, acc1);
            acc2 = fmaf(a, f23.x, acc2);
            acc3 = fmaf(a, f23.y, acc3);
        }
    }
#pragma unroll
    for (int o = 16; o > 0; o >>= 1) z += __shfl_xor_sync(0xffffffffu, z, o);

    // epilogue: features f = lane*4 + {0..3}
    float4 bv = ((const float4*)b1)[lane];
    float g0 = fmaxf(acc0 / z + bv.x, 0.f);
    float g1 = fmaxf(acc1 / z + bv.y, 0.f);
    float g2 = fmaxf(acc2 / z + bv.z, 0.f);
    float g3 = fmaxf(acc3 / z + bv.w, 0.f);
    const float4* W24 = (const float4*)W2;    // [f][2] layout
    float4 wA = W24[lane * 2 + 0];            // f, f+1
    float4 wB = W24[lane * 2 + 1];            // f+2, f+3
    float h0 = g0 * wA.x + g1 * wA.z + g2 * wB.x + g3 * wB.z;
    float h1 = g0 * wA.y + g1 * wA.w + g2 * wB.y + g3 * wB.w;
#pragma unroll
    for (int o = 16; o > 0; o >>= 1) {
        h0 += __shfl_down_sync(0xffffffffu, h0, o);
        h1 += __shfl_down_sync(0xffffffffu, h1, o);
    }
    if (lane == 0) {
        g_n2[w] = make_float4(h0, h1,
                              h0 * as2[0] + h1 * as2[1],
                              h0 * ad2[0] + h1 * ad2[1]);
    }
}

// Layer-2: one warp per node, single pass, single packed float4 gather per edge.
__global__ void k_agg2(const float* __restrict__ b2, float* __restrict__ out, int N) {
    int w = blockIdx.x * (blockDim.x >> 5) + (threadIdx.x >> 5);
    int lane = threadIdx.x & 31;
    if (w >= N) return;
    int r0 = g_rowptr[w], r1 = g_rowptr[w + 1];
    float sd = g_n2[w].w;

    float z = 0.f, acc0 = 0.f, acc1 = 0.f;
    for (int p = r0 + lane; p < r1; p += 32) {
        int s = g_csr_src[p];
        float4 v = g_n2[s];
        float ex = __expf(lrelu(v.z + sd));
        z += ex;
        acc0 = fmaf(ex, v.x, acc0);
        acc1 = fmaf(ex, v.y, acc1);
    }
#pragma unroll
    for (int o = 16; o > 0; o >>= 1) {
        z    += __shfl_down_sync(0xffffffffu, z, o);
        acc0 += __shfl_down_sync(0xffffffffu, acc0, o);
        acc1 += __shfl_down_sync(0xffffffffu, acc1, o);
    }
    if (lane == 0) {
        out[w * 2 + 0] = acc0 / z + b2[0];
        out[w * 2 + 1] = acc1 / z + b2[1];
    }
}

// ---------------- launch ----------------
extern "C" void kernel_launch(void* const* d_in, const int* in_sizes, int n_in,
                              void* d_out, int out_size) {
    const float* x      = (const float*)d_in[0];
    const int*   ei     = (const int*)d_in[1];
    const float* W1     = (const float*)d_in[2];
    const float* a_src1 = (const float*)d_in[3];
    const float* a_dst1 = (const float*)d_in[4];
    const float* b1     = (const float*)d_in[5];
    const float* W2     = (const float*)d_in[6];
    const float* a_src2 = (const float*)d_in[7];
    const float* a_dst2 = (const float*)d_in[8];
    const float* b2     = (const float*)d_in[9];
    float*       out    = (float*)d_out;

    int N = in_sizes[0] / F1;
    int E = in_sizes[1] / 2;
    int ET = E + N;
    int NB = (N + 1023) / 1024;

    cudaFuncSetAttribute(k_gemm1, cudaFuncAttributeMaxDynamicSharedMemorySize,
                         GEMM1_SMEM);

    k_zero<<<256, 256>>>(N);
    k_prepW<<<16, 256>>>(W1);
    k_gemm1<<<(N + 63) / 64, 256, GEMM1_SMEM>>>(x, a_src1, a_dst1, N);
    k_deg<<<(E + 255) / 256, 256>>>(ei, E);
    k_scanA<<<NB, 1024>>>(N);
    k_scanB<<<1, 128>>>(NB);
    k_scanC<<<(N + 255) / 256, 256>>>(N, ET);
    k_fill<<<(E + 255) / 256, 256>>>(ei, E);
    k_agg1<<<(N + 7) / 8, 256>>>(b1, W2, a_src2, a_dst2, N);
    k_agg2<<<(N + 7) / 8, 256>>>(b2, out, N);
}